// round 15
// baseline (speedup 1.0000x reference)
#include <cuda_runtime.h>
#include <cstdint>

#define NV   50000
#define NNZV 1600000
#define NB   4
#define FIN  128
#define FOUT 128
#define KORD 5
#define NF   512   // FIN * NB

#define SCAN_NB 196   // ceil(NV/256)

// Scratch (sanctioned __device__ globals; no runtime allocation)
static __device__ float g_x0[(size_t)NV * NF];
static __device__ float g_x1[(size_t)NV * NF];
static __device__ float g_x2[(size_t)NV * NF];
static __device__ float g_x3[(size_t)NV * NF];
static __device__ float g_x4[(size_t)NV * NF];
static __device__ float g_wp[KORD * FIN * FOUT];   // permuted + tf32-rounded weight
static __device__ int   g_rowptr[NV + 1];
static __device__ int   g_cursor[NV];
static __device__ int   g_cnt[NV];
static __device__ int   g_partial[SCAN_NB];
static __device__ int   g_pstart[SCAN_NB];
static __device__ int   g_cols[NNZV];
static __device__ float g_vals[NNZV];

__device__ __forceinline__ unsigned f2tf32(float x) {
    unsigned r;
    asm("cvt.rna.tf32.f32 %0, %1;" : "=r"(r) : "f"(x));
    return r;
}

__global__ void zero_cnt_k() {
    int i = blockIdx.x * blockDim.x + threadIdx.x;
    if (i < NV) g_cnt[i] = 0;
}

__global__ void hist_k(const int* __restrict__ rows) {
    int i = blockIdx.x * blockDim.x + threadIdx.x;
    if (i < NNZV) atomicAdd(&g_cnt[rows[i]], 1);
}

// ---------- multi-block 3-phase scan ----------
__global__ void scan1_k() {
    __shared__ int wsum[8];
    int i = blockIdx.x * 256 + threadIdx.x;
    int v = (i < NV) ? g_cnt[i] : 0;
    int lane = threadIdx.x & 31, warp = threadIdx.x >> 5;
#pragma unroll
    for (int off = 16; off > 0; off >>= 1)
        v += __shfl_down_sync(0xffffffffu, v, off);
    if (lane == 0) wsum[warp] = v;
    __syncthreads();
    if (threadIdx.x == 0) {
        int s = 0;
#pragma unroll
        for (int w = 0; w < 8; w++) s += wsum[w];
        g_partial[blockIdx.x] = s;
    }
}

__global__ void scan2_k() {
    __shared__ int wsum[8];
    int t = threadIdx.x;            // 256 threads
    int v = (t < SCAN_NB) ? g_partial[t] : 0;
    int lane = t & 31, warp = t >> 5;
    int inc = v;
#pragma unroll
    for (int off = 1; off < 32; off <<= 1) {
        int n = __shfl_up_sync(0xffffffffu, inc, off);
        if (lane >= off) inc += n;
    }
    if (lane == 31) wsum[warp] = inc;
    __syncthreads();
    if (warp == 0 && lane < 8) {
        int w = wsum[lane];
#pragma unroll
        for (int off = 1; off < 8; off <<= 1) {
            int n = __shfl_up_sync(0xffu, w, off);
            if (lane >= off) w += n;
        }
        wsum[lane] = w;
    }
    __syncthreads();
    int ex = (inc - v) + (warp ? wsum[warp - 1] : 0);
    if (t < SCAN_NB) g_pstart[t] = ex;
}

__global__ void scan3_k() {
    __shared__ int wsum[8];
    int i = blockIdx.x * 256 + threadIdx.x;
    int c = (i < NV) ? g_cnt[i] : 0;
    int lane = threadIdx.x & 31, warp = threadIdx.x >> 5;
    int inc = c;
#pragma unroll
    for (int off = 1; off < 32; off <<= 1) {
        int n = __shfl_up_sync(0xffffffffu, inc, off);
        if (lane >= off) inc += n;
    }
    if (lane == 31) wsum[warp] = inc;
    __syncthreads();
    if (warp == 0 && lane < 8) {
        int w = wsum[lane];
#pragma unroll
        for (int off = 1; off < 8; off <<= 1) {
            int n = __shfl_up_sync(0xffu, w, off);
            if (lane >= off) w += n;
        }
        wsum[lane] = w;
    }
    __syncthreads();
    int ex = (inc - c) + (warp ? wsum[warp - 1] : 0) + g_pstart[blockIdx.x];
    if (i < NV) {
        g_cursor[i] = ex;
        g_rowptr[i + 1] = ex + c;
    }
    if (i == 0) g_rowptr[0] = 0;
}

__global__ void scatter_k(const int* __restrict__ rows, const int* __restrict__ cols,
                          const float* __restrict__ vals) {
    int i = blockIdx.x * blockDim.x + threadIdx.x;
    if (i < NNZV) {
        int r = rows[i];
        int p = atomicAdd(&g_cursor[r], 1);
        g_cols[p] = cols[i];
        g_vals[p] = vals[i];
    }
}

// inputs [B,V,FIN] -> g_x0 [V, b*FIN+f]
__global__ void transpose_k(const float* __restrict__ inputs) {
    int i4 = blockIdx.x * blockDim.x + threadIdx.x;   // over NV*NF/4
    if (i4 >= NV * NF / 4) return;
    int v  = i4 >> 7;       // NF/4 = 128 float4 per row
    int c4 = i4 & 127;
    float4 val = ((const float4*)inputs)[((size_t)((c4 >> 5) * NV + v) << 5) + (c4 & 31)];
    ((float4*)g_x0)[i4] = val;
}

// wp[kk][fo] for kk = kb*128 + fi  ->  weight[(fi*KORD + kb)*FOUT + fo], tf32-rounded.
// (replicates reference's (Fin,K)-vs-(K,Fin) flatten mismatch)
__global__ void permute_w_k(const float* __restrict__ weight) {
    int idx = blockIdx.x * blockDim.x + threadIdx.x;   // over 640*128
    if (idx >= KORD * FIN * FOUT) return;
    int kk = idx >> 7, fo = idx & 127;
    int kb = kk >> 7, fi = kk & 127;
    unsigned t = f2tf32(weight[(fi * KORD + kb) * FOUT + fo]);
    ((unsigned*)g_wp)[idx] = t;
}

// One block (128 threads) per output row: y[r,:] = sum_j vals[j] * x[cols[j],:]
// cheb: y = 2*acc - xprev[r,:]
__global__ void spmm_k(const float* __restrict__ x, const float* __restrict__ xprev,
                       float* __restrict__ y, int cheb) {
    int r = blockIdx.x;
    int t = threadIdx.x;
    int s = g_rowptr[r], e = g_rowptr[r + 1];
    float ax = 0.f, ay = 0.f, az = 0.f, aw = 0.f;
#pragma unroll 4
    for (int j = s; j < e; j++) {
        int   c = g_cols[j];
        float v = g_vals[j];
        float4 xv = ((const float4*)(x + ((size_t)c << 9)))[t];
        ax += v * xv.x; ay += v * xv.y; az += v * xv.z; aw += v * xv.w;
    }
    float4 res;
    if (cheb) {
        float4 p = ((const float4*)(xprev + ((size_t)r << 9)))[t];
        res.x = 2.f * ax - p.x; res.y = 2.f * ay - p.y;
        res.z = 2.f * az - p.z; res.w = 2.f * aw - p.w;
    } else {
        res.x = ax; res.y = ay; res.z = az; res.w = aw;
    }
    ((float4*)(y + ((size_t)r << 9)))[t] = res;
}

// ============================ fused tf32 tensor-core GEMM ============================
// out[b, v0:v0+128, :] = sum over K=640 of A[v, kk] * wp[kk][:]  + bias
// A[v, kb*128 + j] = x_kb[v*512 + b*128 + j]
// 4-stage cp.async ring, k-chunk 8 (80 chunks), static smem 42KB.
#define APITCH 12
#define WPITCH 136
#define A_FLOATS (128 * APITCH)          // per stage = 1536 floats
#define W_FLOATS (8 * WPITCH)            // per stage = 1088 floats
#define NSTAGE 4
#define NCHUNK 80                        // 5 buffers x 16 k-chunks of 8

__device__ __forceinline__ void cpasync16(unsigned dst, const void* src, int bytes) {
    asm volatile("cp.async.cg.shared.global [%0], [%1], 16, %2;\n"
                 :: "r"(dst), "l"(src), "r"(bytes));
}

__device__ __forceinline__ void mma_tf32(float* c, const unsigned* a, const unsigned* b) {
    asm volatile(
        "mma.sync.aligned.m16n8k8.row.col.f32.tf32.tf32.f32 "
        "{%0,%1,%2,%3}, {%4,%5,%6,%7}, {%8,%9}, {%0,%1,%2,%3};"
        : "+f"(c[0]), "+f"(c[1]), "+f"(c[2]), "+f"(c[3])
        : "r"(a[0]), "r"(a[1]), "r"(a[2]), "r"(a[3]), "r"(b[0]), "r"(b[1]));
}

__global__ void __launch_bounds__(256)
gemm_tc_k(const float* __restrict__ x0, const float* __restrict__ x1,
          const float* __restrict__ x2, const float* __restrict__ x3,
          const float* __restrict__ x4,
          const float* __restrict__ bias, float* __restrict__ out) {
    __shared__ float Asm[NSTAGE][A_FLOATS];
    __shared__ float Wsm[NSTAGE][W_FLOATS];

    int tid  = threadIdx.x;
    int bidx = blockIdx.y;
    int v0   = blockIdx.x << 7;
    int lane = tid & 31;
    int warp = tid >> 5;
    int wm = warp >> 1, wn = warp & 1;
    int lr = lane >> 2, lc = lane & 3;
    int boff = bidx << 7;

    const float* wp = g_wp;

    float acc[2][8][4];
#pragma unroll
    for (int mt = 0; mt < 2; mt++)
#pragma unroll
        for (int nt = 0; nt < 8; nt++)
#pragma unroll
            for (int q = 0; q < 4; q++) acc[mt][nt][q] = 0.f;

    unsigned abase[NSTAGE], wbase[NSTAGE];
#pragma unroll
    for (int s = 0; s < NSTAGE; s++) {
        abase[s] = (unsigned)__cvta_generic_to_shared(&Asm[s][0]);
        wbase[s] = (unsigned)__cvta_generic_to_shared(&Wsm[s][0]);
    }

    // issue chunk c into stage c % NSTAGE
    auto issue = [&](int c) {
        if (c < NCHUNK) {
            int kb = c >> 4, kc = c & 15;
            const float* xb = (kb == 0) ? x0 : (kb == 1) ? x1 : (kb == 2) ? x2
                              : (kb == 3) ? x3 : x4;
            int stage = c & (NSTAGE - 1);
            // A: 128 rows x 8 floats = 256 float4; 1 per thread
            {
                int r = tid >> 1, cc = tid & 1;
                int v = v0 + r;
                int valid = (v < NV) ? 16 : 0;
                int vs = (v < NV) ? v : 0;
                const float* src = xb + ((size_t)vs << 9) + boff + (kc << 3) + (cc << 2);
                cpasync16(abase[stage] + (unsigned)(r * APITCH + (cc << 2)) * 4u, src, valid);
            }
            // W: 8 rows x 128 floats = 256 float4; 1 per thread
            {
                int r = tid >> 5, cc = tid & 31;
                const float* src = wp + (((kb << 7) + (kc << 3) + r) << 7) + (cc << 2);
                cpasync16(wbase[stage] + (unsigned)(r * WPITCH + (cc << 2)) * 4u, src, 16);
            }
        }
        asm volatile("cp.async.commit_group;");
    };

    // prime NSTAGE-1 stages
    issue(0); issue(1); issue(2);

    for (int c = 0; c < NCHUNK; c++) {
        issue(c + NSTAGE - 1);
        // groups complete in order; <=3 newer outstanding => chunk c resident
        asm volatile("cp.async.wait_group %0;" :: "n"(NSTAGE - 1));
        __syncthreads();

        int stage = c & (NSTAGE - 1);
        const float* As = Asm[stage];
        const float* Ws = Wsm[stage];
        int m_base = wm << 5;
        int n_base = wn << 6;

        unsigned af[2][4];
#pragma unroll
        for (int mt = 0; mt < 2; mt++) {
            int r0 = m_base + (mt << 4) + lr;
            af[mt][0] = f2tf32(As[r0 * APITCH + lc]);
            af[mt][1] = f2tf32(As[(r0 + 8) * APITCH + lc]);
            af[mt][2] = f2tf32(As[r0 * APITCH + lc + 4]);
            af[mt][3] = f2tf32(As[(r0 + 8) * APITCH + lc + 4]);
        }
        unsigned bf[8][2];
#pragma unroll
        for (int nt = 0; nt < 8; nt++) {
            int col = n_base + (nt << 3) + lr;
            bf[nt][0] = __float_as_uint(Ws[lc * WPITCH + col]);
            bf[nt][1] = __float_as_uint(Ws[(lc + 4) * WPITCH + col]);
        }
#pragma unroll
        for (int mt = 0; mt < 2; mt++)
#pragma unroll
            for (int nt = 0; nt < 8; nt++)
                mma_tf32(acc[mt][nt], af[mt], bf[nt]);

        __syncthreads();   // all reads of this stage done before it is re-filled
    }

    // epilogue: bias + store (c0,c1 adjacent cols -> float2)
#pragma unroll
    for (int mt = 0; mt < 2; mt++) {
        int r0 = v0 + (wm << 5) + (mt << 4) + lr;
#pragma unroll
        for (int nt = 0; nt < 8; nt++) {
            int col = (wn << 6) + (nt << 3) + (lc << 1);
            float2 bv = *(const float2*)(bias + col);
            if (r0 < NV) {
                float2 o0 = make_float2(acc[mt][nt][0] + bv.x, acc[mt][nt][1] + bv.y);
                *(float2*)(out + (((size_t)bidx * NV + r0) << 7) + col) = o0;
            }
            if (r0 + 8 < NV) {
                float2 o1 = make_float2(acc[mt][nt][2] + bv.x, acc[mt][nt][3] + bv.y);
                *(float2*)(out + (((size_t)bidx * NV + r0 + 8) << 7) + col) = o1;
            }
        }
    }
}

extern "C" void kernel_launch(void* const* d_in, const int* in_sizes, int n_in,
                              void* d_out, int out_size) {
    const int*   rows   = (const int*)d_in[0];
    const int*   cols   = (const int*)d_in[1];
    const float* vals   = (const float*)d_in[2];
    const float* inputs = (const float*)d_in[3];
    const float* weight = (const float*)d_in[4];
    const float* bias   = (const float*)d_in[5];
    float*       out    = (float*)d_out;

    float *x0, *x1, *x2, *x3, *x4;
    cudaGetSymbolAddress((void**)&x0, g_x0);
    cudaGetSymbolAddress((void**)&x1, g_x1);
    cudaGetSymbolAddress((void**)&x2, g_x2);
    cudaGetSymbolAddress((void**)&x3, g_x3);
    cudaGetSymbolAddress((void**)&x4, g_x4);

    // CSR build + weight permute
    zero_cnt_k<<<(NV + 255) / 256, 256>>>();
    hist_k<<<(NNZV + 255) / 256, 256>>>(rows);
    permute_w_k<<<(KORD * FIN * FOUT + 255) / 256, 256>>>(weight);
    scan1_k<<<SCAN_NB, 256>>>();
    scan2_k<<<1, 256>>>();
    scan3_k<<<SCAN_NB, 256>>>();
    scatter_k<<<(NNZV + 255) / 256, 256>>>(rows, cols, vals);

    // x0 and Chebyshev recurrence
    transpose_k<<<(NV * NF / 4 + 255) / 256, 256>>>(inputs);
    spmm_k<<<NV, 128>>>(x0, nullptr, x1, 0);
    spmm_k<<<NV, 128>>>(x1, x0, x2, 1);
    spmm_k<<<NV, 128>>>(x2, x1, x3, 1);
    spmm_k<<<NV, 128>>>(x3, x2, x4, 1);

    // fused tensor-core GEMM over K = 640
    dim3 ggrid((NV + 127) / 128, NB);
    gemm_tc_k<<<ggrid, 256>>>(x0, x1, x2, x3, x4, bias, out);
}

// round 17
// speedup vs baseline: 1.4683x; 1.4683x over previous
#include <cuda_runtime.h>
#include <cuda_fp16.h>
#include <cstdint>

#define NV   50000
#define NNZV 1600000
#define NB   4
#define FIN  128
#define FOUT 128
#define KORD 5
#define NF   512   // FIN * NB

#define SCAN_NB 196   // ceil(NV/256)

// Scratch (sanctioned __device__ globals; no runtime allocation)
static __device__ __half g_x0[(size_t)NV * NF];
static __device__ __half g_x1[(size_t)NV * NF];
static __device__ __half g_x2[(size_t)NV * NF];
static __device__ __half g_x3[(size_t)NV * NF];
static __device__ __half g_x4[(size_t)NV * NF];
static __device__ float  g_wp[KORD * FIN * FOUT];   // permuted + tf32-rounded weight
static __device__ int    g_rowptr[NV + 1];
static __device__ int    g_cursor[NV];
static __device__ int    g_cnt[NV];
static __device__ int    g_partial[SCAN_NB];
static __device__ int    g_pstart[SCAN_NB];
static __device__ int    g_cols[NNZV];
static __device__ float  g_vals[NNZV];

__device__ __forceinline__ unsigned f2tf32(float x) {
    unsigned r;
    asm("cvt.rna.tf32.f32 %0, %1;" : "=r"(r) : "f"(x));
    return r;
}

__global__ void zero_cnt_k() {
    int i = blockIdx.x * blockDim.x + threadIdx.x;
    if (i < NV) g_cnt[i] = 0;
}

__global__ void hist_k(const int* __restrict__ rows) {
    int i = blockIdx.x * blockDim.x + threadIdx.x;
    if (i < NNZV) atomicAdd(&g_cnt[rows[i]], 1);
}

// ---------- multi-block 3-phase scan ----------
__global__ void scan1_k() {
    __shared__ int wsum[8];
    int i = blockIdx.x * 256 + threadIdx.x;
    int v = (i < NV) ? g_cnt[i] : 0;
    int lane = threadIdx.x & 31, warp = threadIdx.x >> 5;
#pragma unroll
    for (int off = 16; off > 0; off >>= 1)
        v += __shfl_down_sync(0xffffffffu, v, off);
    if (lane == 0) wsum[warp] = v;
    __syncthreads();
    if (threadIdx.x == 0) {
        int s = 0;
#pragma unroll
        for (int w = 0; w < 8; w++) s += wsum[w];
        g_partial[blockIdx.x] = s;
    }
}

__global__ void scan2_k() {
    __shared__ int wsum[8];
    int t = threadIdx.x;            // 256 threads
    int v = (t < SCAN_NB) ? g_partial[t] : 0;
    int lane = t & 31, warp = t >> 5;
    int inc = v;
#pragma unroll
    for (int off = 1; off < 32; off <<= 1) {
        int n = __shfl_up_sync(0xffffffffu, inc, off);
        if (lane >= off) inc += n;
    }
    if (lane == 31) wsum[warp] = inc;
    __syncthreads();
    if (warp == 0 && lane < 8) {
        int w = wsum[lane];
#pragma unroll
        for (int off = 1; off < 8; off <<= 1) {
            int n = __shfl_up_sync(0xffu, w, off);
            if (lane >= off) w += n;
        }
        wsum[lane] = w;
    }
    __syncthreads();
    int ex = (inc - v) + (warp ? wsum[warp - 1] : 0);
    if (t < SCAN_NB) g_pstart[t] = ex;
}

__global__ void scan3_k() {
    __shared__ int wsum[8];
    int i = blockIdx.x * 256 + threadIdx.x;
    int c = (i < NV) ? g_cnt[i] : 0;
    int lane = threadIdx.x & 31, warp = threadIdx.x >> 5;
    int inc = c;
#pragma unroll
    for (int off = 1; off < 32; off <<= 1) {
        int n = __shfl_up_sync(0xffffffffu, inc, off);
        if (lane >= off) inc += n;
    }
    if (lane == 31) wsum[warp] = inc;
    __syncthreads();
    if (warp == 0 && lane < 8) {
        int w = wsum[lane];
#pragma unroll
        for (int off = 1; off < 8; off <<= 1) {
            int n = __shfl_up_sync(0xffu, w, off);
            if (lane >= off) w += n;
        }
        wsum[lane] = w;
    }
    __syncthreads();
    int ex = (inc - c) + (warp ? wsum[warp - 1] : 0) + g_pstart[blockIdx.x];
    if (i < NV) {
        g_cursor[i] = ex;
        g_rowptr[i + 1] = ex + c;
    }
    if (i == 0) g_rowptr[0] = 0;
}

__global__ void scatter_k(const int* __restrict__ rows, const int* __restrict__ cols,
                          const float* __restrict__ vals) {
    int i = blockIdx.x * blockDim.x + threadIdx.x;
    if (i < NNZV) {
        int r = rows[i];
        int p = atomicAdd(&g_cursor[r], 1);
        g_cols[p] = cols[i];
        g_vals[p] = vals[i];
    }
}

// inputs [B,V,FIN] f32 -> g_x0 [V, b*FIN+f] fp16
__global__ void transpose_k(const float* __restrict__ inputs) {
    int i4 = blockIdx.x * blockDim.x + threadIdx.x;   // over NV*NF/4
    if (i4 >= NV * NF / 4) return;
    int v  = i4 >> 7;       // 128 groups-of-4 per row
    int c4 = i4 & 127;
    float4 val = ((const float4*)inputs)[((size_t)((c4 >> 5) * NV + v) << 5) + (c4 & 31)];
    __half2 h0 = __floats2half2_rn(val.x, val.y);
    __half2 h1 = __floats2half2_rn(val.z, val.w);
    uint2 packed = make_uint2(*(unsigned*)&h0, *(unsigned*)&h1);
    ((uint2*)g_x0)[i4] = packed;
}

// wp[kk][fo] for kk = kb*128 + fi  ->  weight[(fi*KORD + kb)*FOUT + fo], tf32-rounded.
// (replicates reference's (Fin,K)-vs-(K,Fin) flatten mismatch)
__global__ void permute_w_k(const float* __restrict__ weight) {
    int idx = blockIdx.x * blockDim.x + threadIdx.x;   // over 640*128
    if (idx >= KORD * FIN * FOUT) return;
    int kk = idx >> 7, fo = idx & 127;
    int kb = kk >> 7, fi = kk & 127;
    unsigned t = f2tf32(weight[(fi * KORD + kb) * FOUT + fo]);
    ((unsigned*)g_wp)[idx] = t;
}

// One block (128 threads) per output row: y[r,:] = sum_j vals[j] * x[cols[j],:]
// cheb: y = 2*acc - xprev[r,:].  fp16 storage, fp32 accumulate.
__global__ void spmm_k(const __half* __restrict__ x, const __half* __restrict__ xprev,
                       __half* __restrict__ y, int cheb) {
    int r = blockIdx.x;
    int t = threadIdx.x;
    int s = g_rowptr[r], e = g_rowptr[r + 1];
    float a0 = 0.f, a1 = 0.f, a2 = 0.f, a3 = 0.f;
#pragma unroll 4
    for (int j = s; j < e; j++) {
        int   c = g_cols[j];
        float v = g_vals[j];
        uint2 raw = ((const uint2*)(x + ((size_t)c << 9)))[t];
        float2 f0 = __half22float2(*(__half2*)&raw.x);
        float2 f1 = __half22float2(*(__half2*)&raw.y);
        a0 += v * f0.x; a1 += v * f0.y; a2 += v * f1.x; a3 += v * f1.y;
    }
    if (cheb) {
        uint2 praw = ((const uint2*)(xprev + ((size_t)r << 9)))[t];
        float2 p0 = __half22float2(*(__half2*)&praw.x);
        float2 p1 = __half22float2(*(__half2*)&praw.y);
        a0 = 2.f * a0 - p0.x; a1 = 2.f * a1 - p0.y;
        a2 = 2.f * a2 - p1.x; a3 = 2.f * a3 - p1.y;
    }
    __half2 h0 = __floats2half2_rn(a0, a1);
    __half2 h1 = __floats2half2_rn(a2, a3);
    ((uint2*)(y + ((size_t)r << 9)))[t] = make_uint2(*(unsigned*)&h0, *(unsigned*)&h1);
}

// ============================ fused tf32 tensor-core GEMM ============================
// out[b, v0:v0+128, :] = sum over K=640 of A[v, kk] * wp[kk][:]  + bias
// A[v, kb*128 + j] = x_kb[v*512 + b*128 + j]  (fp16 global, converted to tf32 at frag load)
// Proven config: k-chunk 16, 2 stages. A smem fp16 pitch 24 halfs.
#define APITCH_H 24
#define WPITCH 136
#define A_HALFS (128 * APITCH_H)         // per stage = 3072 halfs (6KB)
#define W_FLOATS (16 * WPITCH)           // per stage = 2176 floats
#define NCHUNK 40                        // 5 buffers x 8 k-chunks of 16

__device__ __forceinline__ void cpasync16(unsigned dst, const void* src, int bytes) {
    asm volatile("cp.async.cg.shared.global [%0], [%1], 16, %2;\n"
                 :: "r"(dst), "l"(src), "r"(bytes));
}

__device__ __forceinline__ unsigned h2tf32(__half h) {
    return f2tf32(__half2float(h));
}

__device__ __forceinline__ void mma_tf32(float* c, const unsigned* a, const unsigned* b) {
    asm volatile(
        "mma.sync.aligned.m16n8k8.row.col.f32.tf32.tf32.f32 "
        "{%0,%1,%2,%3}, {%4,%5,%6,%7}, {%8,%9}, {%0,%1,%2,%3};"
        : "+f"(c[0]), "+f"(c[1]), "+f"(c[2]), "+f"(c[3])
        : "r"(a[0]), "r"(a[1]), "r"(a[2]), "r"(a[3]), "r"(b[0]), "r"(b[1]));
}

__global__ void __launch_bounds__(256)
gemm_tc_k(const __half* __restrict__ x0, const __half* __restrict__ x1,
          const __half* __restrict__ x2, const __half* __restrict__ x3,
          const __half* __restrict__ x4,
          const float* __restrict__ bias, float* __restrict__ out) {
    __shared__ __half Asm[2][A_HALFS];
    __shared__ float  Wsm[2][W_FLOATS];

    int tid  = threadIdx.x;
    int bidx = blockIdx.y;
    int v0   = blockIdx.x << 7;
    int lane = tid & 31;
    int warp = tid >> 5;
    int wm = warp >> 1, wn = warp & 1;
    int lr = lane >> 2, lc = lane & 3;
    int boff = bidx << 7;

    const float* wp = g_wp;

    float acc[2][8][4];
#pragma unroll
    for (int mt = 0; mt < 2; mt++)
#pragma unroll
        for (int nt = 0; nt < 8; nt++)
#pragma unroll
            for (int q = 0; q < 4; q++) acc[mt][nt][q] = 0.f;

    unsigned abase0 = (unsigned)__cvta_generic_to_shared(&Asm[0][0]);
    unsigned abase1 = (unsigned)__cvta_generic_to_shared(&Asm[1][0]);
    unsigned wbase0 = (unsigned)__cvta_generic_to_shared(&Wsm[0][0]);
    unsigned wbase1 = (unsigned)__cvta_generic_to_shared(&Wsm[1][0]);

    // issue chunk c into stage c&1
    auto issue = [&](int c) {
        if (c < NCHUNK) {
            int kb = c >> 3, kc = c & 7;
            const __half* xb = (kb == 0) ? x0 : (kb == 1) ? x1 : (kb == 2) ? x2
                               : (kb == 3) ? x3 : x4;
            int stage = c & 1;
            unsigned abase = stage ? abase1 : abase0;
            unsigned wbase = stage ? wbase1 : wbase0;
            // A: 128 rows x 16 halfs (32B) = 256 x 16B; 1 per thread
            {
                int r = tid >> 1, cc = tid & 1;      // cc: 8-half chunk
                int v = v0 + r;
                int valid = (v < NV) ? 16 : 0;
                int vs = (v < NV) ? v : 0;
                const __half* src = xb + ((size_t)vs << 9) + boff + (kc << 4) + (cc << 3);
                cpasync16(abase + (unsigned)(r * APITCH_H + (cc << 3)) * 2u, src, valid);
            }
            // W: 16 rows x 128 floats = 512 float4; 2 per thread
#pragma unroll
            for (int i = 0; i < 2; i++) {
                int lin = tid + (i << 8);
                int r = lin >> 5, cc = lin & 31;
                const float* src = wp + (((kb << 7) + (kc << 4) + r) << 7) + (cc << 2);
                cpasync16(wbase + (unsigned)(r * WPITCH + (cc << 2)) * 4u, src, 16);
            }
        }
        asm volatile("cp.async.commit_group;");
    };

    issue(0);

    for (int c = 0; c < NCHUNK; c++) {
        asm volatile("cp.async.wait_group 0;");
        __syncthreads();
        issue(c + 1);

        int stage = c & 1;
        const __half* As = Asm[stage];
        const float*  Ws = Wsm[stage];
        int m_base = wm << 5;
        int n_base = wn << 6;

#pragma unroll
        for (int s = 0; s < 2; s++) {
            unsigned af[2][4];
#pragma unroll
            for (int mt = 0; mt < 2; mt++) {
                int r0 = m_base + (mt << 4) + lr;
                int c0 = (s << 3) + lc;
                af[mt][0] = h2tf32(As[r0 * APITCH_H + c0]);
                af[mt][1] = h2tf32(As[(r0 + 8) * APITCH_H + c0]);
                af[mt][2] = h2tf32(As[r0 * APITCH_H + c0 + 4]);
                af[mt][3] = h2tf32(As[(r0 + 8) * APITCH_H + c0 + 4]);
            }
            unsigned bf[8][2];
#pragma unroll
            for (int nt = 0; nt < 8; nt++) {
                int col = n_base + (nt << 3) + lr;
                bf[nt][0] = __float_as_uint(Ws[((s << 3) + lc) * WPITCH + col]);
                bf[nt][1] = __float_as_uint(Ws[((s << 3) + 4 + lc) * WPITCH + col]);
            }
#pragma unroll
            for (int mt = 0; mt < 2; mt++)
#pragma unroll
                for (int nt = 0; nt < 8; nt++)
                    mma_tf32(acc[mt][nt], af[mt], bf[nt]);
        }
        __syncthreads();
    }

    // epilogue: bias + store (c0,c1 adjacent cols -> float2)
#pragma unroll
    for (int mt = 0; mt < 2; mt++) {
        int r0 = v0 + (wm << 5) + (mt << 4) + lr;
#pragma unroll
        for (int nt = 0; nt < 8; nt++) {
            int col = (wn << 6) + (nt << 3) + (lc << 1);
            float2 bv = *(const float2*)(bias + col);
            if (r0 < NV) {
                float2 o0 = make_float2(acc[mt][nt][0] + bv.x, acc[mt][nt][1] + bv.y);
                *(float2*)(out + (((size_t)bidx * NV + r0) << 7) + col) = o0;
            }
            if (r0 + 8 < NV) {
                float2 o1 = make_float2(acc[mt][nt][2] + bv.x, acc[mt][nt][3] + bv.y);
                *(float2*)(out + (((size_t)bidx * NV + r0 + 8) << 7) + col) = o1;
            }
        }
    }
}

extern "C" void kernel_launch(void* const* d_in, const int* in_sizes, int n_in,
                              void* d_out, int out_size) {
    const int*   rows   = (const int*)d_in[0];
    const int*   cols   = (const int*)d_in[1];
    const float* vals   = (const float*)d_in[2];
    const float* inputs = (const float*)d_in[3];
    const float* weight = (const float*)d_in[4];
    const float* bias   = (const float*)d_in[5];
    float*       out    = (float*)d_out;

    __half *x0, *x1, *x2, *x3, *x4;
    cudaGetSymbolAddress((void**)&x0, g_x0);
    cudaGetSymbolAddress((void**)&x1, g_x1);
    cudaGetSymbolAddress((void**)&x2, g_x2);
    cudaGetSymbolAddress((void**)&x3, g_x3);
    cudaGetSymbolAddress((void**)&x4, g_x4);

    // CSR build + weight permute
    zero_cnt_k<<<(NV + 255) / 256, 256>>>();
    hist_k<<<(NNZV + 255) / 256, 256>>>(rows);
    permute_w_k<<<(KORD * FIN * FOUT + 255) / 256, 256>>>(weight);
    scan1_k<<<SCAN_NB, 256>>>();
    scan2_k<<<1, 256>>>();
    scan3_k<<<SCAN_NB, 256>>>();
    scatter_k<<<(NNZV + 255) / 256, 256>>>(rows, cols, vals);

    // x0 and Chebyshev recurrence (fp16 buffers)
    transpose_k<<<(NV * NF / 4 + 255) / 256, 256>>>(inputs);
    spmm_k<<<NV, 128>>>(x0, nullptr, x1, 0);
    spmm_k<<<NV, 128>>>(x1, x0, x2, 1);
    spmm_k<<<NV, 128>>>(x2, x1, x3, 1);
    spmm_k<<<NV, 128>>>(x3, x2, x4, 1);

    // fused tensor-core GEMM over K = 640
    dim3 ggrid((NV + 127) / 128, NB);
    gemm_tc_k<<<ggrid, 256>>>(x0, x1, x2, x3, x4, bias, out);
}